// round 1
// baseline (speedup 1.0000x reference)
#include <cuda_runtime.h>
#include <cuda_bf16.h>

// Problem constants
#define BB 2
#define TT 2048
#define DD 2048
#define NH 32
#define NKV 8
#define HD 64
#define MM (BB*TT)            // 4096 rows
#define QKV_N 3072            // D + 2*KV_DIM
#define KV_OFF 2048
#define V_OFF 2560

// Scratch (allocation-free rule: __device__ globals)
__device__ float g_qkv[(size_t)MM * QKV_N];   // 50.3 MB
__device__ float g_att[(size_t)MM * DD];      // 33.5 MB

// ---------------------------------------------------------------------------
// SGEMM: C[M,N] = A[M,K] * B[K,N], all row-major. 64x64 tile, BK=16, 256 thr,
// 4x4 per-thread microtile. Assumes M,N % 64 == 0, K % 16 == 0 (true here).
// ---------------------------------------------------------------------------
__global__ __launch_bounds__(256) void sgemm64(
    const float* __restrict__ A, const float* __restrict__ Bw,
    float* __restrict__ C, int Mm, int Nn, int Kk)
{
    __shared__ float As[16][64];   // transposed A tile: As[k][m]
    __shared__ float Bs[16][64];   // Bs[k][n]
    const int tid = threadIdx.x;
    const int tx = tid & 15, ty = tid >> 4;
    const int rowBase = blockIdx.y * 64;
    const int colBase = blockIdx.x * 64;

    float c[4][4] = {};

    for (int k0 = 0; k0 < Kk; k0 += 16) {
        // Load A tile 64x16 (4 floats/thread, float4)
        {
            int e = tid * 4;            // 0..1023
            int r = e >> 4, cc = e & 15;
            float4 v = *(const float4*)&A[(size_t)(rowBase + r) * Kk + k0 + cc];
            As[cc + 0][r] = v.x; As[cc + 1][r] = v.y;
            As[cc + 2][r] = v.z; As[cc + 3][r] = v.w;
        }
        // Load B tile 16x64
        {
            int e = tid * 4;
            int r = e >> 6, cc = e & 63;
            *(float4*)&Bs[r][cc] =
                *(const float4*)&Bw[(size_t)(k0 + r) * Nn + colBase + cc];
        }
        __syncthreads();

#pragma unroll
        for (int kk = 0; kk < 16; kk++) {
            float4 a4 = *(const float4*)&As[kk][ty * 4];
            float4 b4 = *(const float4*)&Bs[kk][tx * 4];
            float a[4] = {a4.x, a4.y, a4.z, a4.w};
            float b[4] = {b4.x, b4.y, b4.z, b4.w};
#pragma unroll
            for (int i = 0; i < 4; i++)
#pragma unroll
                for (int j = 0; j < 4; j++)
                    c[i][j] += a[i] * b[j];
        }
        __syncthreads();
    }

#pragma unroll
    for (int i = 0; i < 4; i++) {
        float4 v = {c[i][0], c[i][1], c[i][2], c[i][3]};
        *(float4*)&C[(size_t)(rowBase + ty * 4 + i) * Nn + colBase + tx * 4] = v;
    }
}

// ---------------------------------------------------------------------------
// RoPE applied in-place to q ([0,2048)) and k ([2048,2560)) slices of g_qkv.
// One thread per (row, head, d<32) pair.
// ---------------------------------------------------------------------------
__global__ void rope_kernel(float* __restrict__ qkv,
                            const float* __restrict__ sinp,
                            const float* __restrict__ cosp)
{
    int idx = blockIdx.x * blockDim.x + threadIdx.x;
    const int total = MM * 40 * 32;      // 40 heads (32 q + 8 k), 32 pairs each
    if (idx >= total) return;
    int d    = idx & 31;
    int head = (idx >> 5) % 40;
    int row  = idx / (40 * 32);
    int t    = row % TT;
    int col  = (head < NH) ? head * HD : KV_OFF + (head - NH) * HD;
    float* p = qkv + (size_t)row * QKV_N + col;
    float u1 = p[d], u2 = p[d + 32];
    float c = cosp[t * HD + d];
    float s = sinp[t * HD + d];
    // cos/sin are [ang, ang] concatenated so cos[d+32]==cos[d]
    p[d]      = u1 * c - u2 * s;
    p[d + 32] = u2 * c + u1 * s;
}

// ---------------------------------------------------------------------------
// Causal flash attention, fp32. 1 thread = 1 query row (128 rows / block).
// K/V 64x64 tiles staged in smem; online softmax in 16-key chunks.
// grid = (T/128, NH, B), block = 128
// ---------------------------------------------------------------------------
__global__ __launch_bounds__(128) void attn_kernel(
    const float* __restrict__ qkv, float* __restrict__ out)
{
    __shared__ float Ks[64][64];
    __shared__ float Vs[64][64];

    const int b = blockIdx.z, h = blockIdx.y;
    const int qbase = blockIdx.x * 128;
    const int tid = threadIdx.x;
    const int qrow = qbase + tid;
    const int g = h >> 2;                    // kv head (repeat=4)
    const float scale = 0.125f;              // 1/sqrt(64)

    const float* qp = qkv + (size_t)(b * TT + qrow) * QKV_N + h * HD;
    float q[64];
#pragma unroll
    for (int d4 = 0; d4 < 16; d4++) {
        float4 v = *(const float4*)&qp[d4 * 4];
        q[d4*4+0] = v.x * scale; q[d4*4+1] = v.y * scale;
        q[d4*4+2] = v.z * scale; q[d4*4+3] = v.w * scale;
    }

    float acc[64] = {};
    float m = -1e30f, l = 0.f;

    const int ntiles = qbase / 64 + 2;       // tiles needed for causal range
    for (int kt = 0; kt < ntiles; kt++) {
        const int kb = kt * 64;
        // stage K,V tiles (float4, coalesced)
        const float* kp = qkv + (size_t)(b * TT + kb) * QKV_N + KV_OFF + g * HD;
        const float* vp = qkv + (size_t)(b * TT + kb) * QKV_N + V_OFF + g * HD;
        for (int e = tid; e < 1024; e += 128) {
            int r = e >> 4, c4 = e & 15;
            ((float4*)Ks)[e] = *(const float4*)&kp[(size_t)r * QKV_N + c4 * 4];
            ((float4*)Vs)[e] = *(const float4*)&vp[(size_t)r * QKV_N + c4 * 4];
        }
        __syncthreads();

        const int jmax = qrow - kb;          // valid keys: j <= jmax
#pragma unroll 1
        for (int c0 = 0; c0 < 64; c0 += 16) {
            float s[16];
            float cmax = -1e30f;
#pragma unroll
            for (int jj = 0; jj < 16; jj++) {
                const int j = c0 + jj;
                const float4* K4 = (const float4*)Ks[j];
                float sv = 0.f;
#pragma unroll
                for (int d4 = 0; d4 < 16; d4++) {
                    float4 kv = K4[d4];
                    sv += q[d4*4+0]*kv.x + q[d4*4+1]*kv.y
                        + q[d4*4+2]*kv.z + q[d4*4+3]*kv.w;
                }
                sv = (j <= jmax) ? sv : -1e30f;
                s[jj] = sv;
                cmax = fmaxf(cmax, sv);
            }
            float mnew = fmaxf(m, cmax);
            float corr = __expf(m - mnew);
            l *= corr;
#pragma unroll
            for (int d = 0; d < 64; d++) acc[d] *= corr;
            m = mnew;
#pragma unroll
            for (int jj = 0; jj < 16; jj++) {
                float p = __expf(s[jj] - m);
                l += p;
                const float4* V4 = (const float4*)Vs[c0 + jj];
#pragma unroll
                for (int d4 = 0; d4 < 16; d4++) {
                    float4 vv = V4[d4];
                    acc[d4*4+0] += p * vv.x; acc[d4*4+1] += p * vv.y;
                    acc[d4*4+2] += p * vv.z; acc[d4*4+3] += p * vv.w;
                }
            }
        }
        __syncthreads();
    }

    const float inv = 1.f / l;
    float* op = out + (size_t)(b * TT + qrow) * DD + h * HD;
#pragma unroll
    for (int d4 = 0; d4 < 16; d4++) {
        float4 v = {acc[d4*4+0]*inv, acc[d4*4+1]*inv,
                    acc[d4*4+2]*inv, acc[d4*4+3]*inv};
        *(float4*)&op[d4 * 4] = v;
    }
}

// ---------------------------------------------------------------------------
extern "C" void kernel_launch(void* const* d_in, const int* in_sizes, int n_in,
                              void* d_out, int out_size)
{
    const float* x     = (const float*)d_in[0];
    const float* sinp  = (const float*)d_in[1];
    const float* cosp  = (const float*)d_in[2];
    const float* w_qkv = (const float*)d_in[3];
    const float* w_out = (const float*)d_in[4];
    float* out = (float*)d_out;

    float *qkv, *att;
    cudaGetSymbolAddress((void**)&qkv, g_qkv);
    cudaGetSymbolAddress((void**)&att, g_att);

    // 1) qkv = x @ w_qkv     [4096,2048] x [2048,3072]
    {
        dim3 grid(QKV_N / 64, MM / 64);
        sgemm64<<<grid, 256>>>(x, w_qkv, qkv, MM, QKV_N, DD);
    }
    // 2) RoPE on q,k slices
    {
        int total = MM * 40 * 32;
        rope_kernel<<<(total + 255) / 256, 256>>>(qkv, sinp, cosp);
    }
    // 3) causal GQA flash attention
    {
        dim3 grid(TT / 128, NH, BB);
        attn_kernel<<<grid, 128>>>(qkv, att);
    }
    // 4) out = att @ w_out    [4096,2048] x [2048,2048]
    {
        dim3 grid(DD / 64, MM / 64);
        sgemm64<<<grid, 256>>>(att, w_out, out, MM, DD, DD);
    }
}

// round 9
// speedup vs baseline: 4.3484x; 4.3484x over previous
#include <cuda_runtime.h>
#include <cuda_bf16.h>
#include <cstdint>

// Problem constants
#define BB 2
#define TT 2048
#define DD 2048
#define NH 32
#define NKV 8
#define HD 64
#define MM (BB*TT)            // 4096 rows
#define QKV_N 3072            // D + 2*KV_DIM
#define KV_OFF 2048
#define V_OFF 2560

// Scratch (allocation-free rule: __device__ globals)
__device__ float g_qkv[(size_t)MM * QKV_N];   // 50.3 MB
__device__ float g_att[(size_t)MM * DD];      // 33.5 MB

__device__ __forceinline__ uint32_t f2tf32(float x) {
    uint32_t r;
    asm("cvt.rna.tf32.f32 %0, %1;" : "=r"(r) : "f"(x));
    return r;
}

__device__ __forceinline__ void mma_tf32(float* d, const uint32_t* a, const uint32_t* b) {
    asm volatile(
        "mma.sync.aligned.m16n8k8.row.col.f32.tf32.tf32.f32 "
        "{%0,%1,%2,%3}, {%4,%5,%6,%7}, {%8,%9}, {%0,%1,%2,%3};"
        : "+f"(d[0]), "+f"(d[1]), "+f"(d[2]), "+f"(d[3])
        : "r"(a[0]), "r"(a[1]), "r"(a[2]), "r"(a[3]), "r"(b[0]), "r"(b[1]));
}

// ---------------------------------------------------------------------------
// TF32 tensor-core GEMM: C[M,N] = A[M,K] * B[K,N], row-major.
// 128x128x32 block tile, 256 threads = 8 warps (4x2), 32x64 warp tile.
// ---------------------------------------------------------------------------
__global__ __launch_bounds__(256, 2) void gemm_tf32(
    const float* __restrict__ A, const float* __restrict__ Bw,
    float* __restrict__ C, int Mm, int Nn, int Kk)
{
    __shared__ uint32_t As[128][36];   // A tile [m][k], pad 32->36
    __shared__ uint32_t Bs[32][136];   // B tile [k][n], pad 128->136

    const int tid  = threadIdx.x;
    const int wid  = tid >> 5;
    const int lane = tid & 31;
    const int wm   = wid & 3;
    const int wn   = wid >> 2;
    const int rowBase = blockIdx.y * 128;
    const int colBase = blockIdx.x * 128;

    float acc[2][8][4] = {};

    for (int k0 = 0; k0 < Kk; k0 += 32) {
        {
            const int c = (tid & 7) * 4;
#pragma unroll
            for (int it = 0; it < 4; it++) {
                const int r = (tid >> 3) + it * 32;
                float4 v = *(const float4*)&A[(size_t)(rowBase + r) * Kk + k0 + c];
                As[r][c + 0] = f2tf32(v.x); As[r][c + 1] = f2tf32(v.y);
                As[r][c + 2] = f2tf32(v.z); As[r][c + 3] = f2tf32(v.w);
            }
        }
        {
            const int c = (tid & 31) * 4;
#pragma unroll
            for (int it = 0; it < 4; it++) {
                const int r = (tid >> 5) + it * 8;
                float4 v = *(const float4*)&Bw[(size_t)(k0 + r) * Nn + colBase + c];
                Bs[r][c + 0] = f2tf32(v.x); Bs[r][c + 1] = f2tf32(v.y);
                Bs[r][c + 2] = f2tf32(v.z); Bs[r][c + 3] = f2tf32(v.w);
            }
        }
        __syncthreads();

#pragma unroll
        for (int kk = 0; kk < 4; kk++) {
            const int k = kk * 8;
            uint32_t a[2][4];
#pragma unroll
            for (int i = 0; i < 2; i++) {
                const int rr0 = wm * 32 + i * 16 + (lane >> 2);
                const int cc0 = k + (lane & 3);
                a[i][0] = As[rr0][cc0];
                a[i][1] = As[rr0 + 8][cc0];
                a[i][2] = As[rr0][cc0 + 4];
                a[i][3] = As[rr0 + 8][cc0 + 4];
            }
            uint32_t b[8][2];
#pragma unroll
            for (int j = 0; j < 8; j++) {
                const int nc = wn * 64 + j * 8 + (lane >> 2);
                b[j][0] = Bs[k + (lane & 3)][nc];
                b[j][1] = Bs[k + 4 + (lane & 3)][nc];
            }
#pragma unroll
            for (int i = 0; i < 2; i++)
#pragma unroll
                for (int j = 0; j < 8; j++)
                    mma_tf32(acc[i][j], a[i], b[j]);
        }
        __syncthreads();
    }

#pragma unroll
    for (int i = 0; i < 2; i++) {
        const int row = rowBase + wm * 32 + i * 16 + (lane >> 2);
#pragma unroll
        for (int j = 0; j < 8; j++) {
            const int col = colBase + wn * 64 + j * 8 + (lane & 3) * 2;
            float2 v0 = {acc[i][j][0], acc[i][j][1]};
            float2 v1 = {acc[i][j][2], acc[i][j][3]};
            *(float2*)&C[(size_t)row * Nn + col] = v0;
            *(float2*)&C[(size_t)(row + 8) * Nn + col] = v1;
        }
    }
}

// ---------------------------------------------------------------------------
// RoPE applied in-place to q ([0,2048)) and k ([2048,2560)) slices of g_qkv.
// ---------------------------------------------------------------------------
__global__ void rope_kernel(float* __restrict__ qkv,
                            const float* __restrict__ sinp,
                            const float* __restrict__ cosp)
{
    int idx = blockIdx.x * blockDim.x + threadIdx.x;
    const int total = MM * 40 * 32;
    if (idx >= total) return;
    int d    = idx & 31;
    int head = (idx >> 5) % 40;
    int row  = idx / (40 * 32);
    int t    = row % TT;
    int col  = (head < NH) ? head * HD : KV_OFF + (head - NH) * HD;
    float* p = qkv + (size_t)row * QKV_N + col;
    float u1 = p[d], u2 = p[d + 32];
    float c = cosp[t * HD + d];
    float s = sinp[t * HD + d];
    p[d]      = u1 * c - u2 * s;
    p[d + 32] = u2 * c + u1 * s;
}

// ---------------------------------------------------------------------------
// Tensor-core causal flash attention (TF32 mma.sync).
// grid = (T/64, NH, B), block = 128 (4 warps, 16 q-rows each).
// Dynamic smem: Ks 64x68 tf32 | Vs 64x72 tf32 | Ps 4x(16x68) tf32 = 53248 B
// ---------------------------------------------------------------------------
#define KS_WORDS (64*68)
#define VS_WORDS (64*72)
#define ATTN_SMEM ((KS_WORDS + VS_WORDS + 4*16*68) * 4)

__global__ __launch_bounds__(128) void attn_tc(
    const float* __restrict__ qkv, float* __restrict__ out)
{
    extern __shared__ uint32_t dyn[];
    uint32_t (*Ks)[68] = (uint32_t(*)[68])dyn;
    uint32_t (*Vs)[72] = (uint32_t(*)[72])(dyn + KS_WORDS);
    const int b = blockIdx.z, h = blockIdx.y;
    const int qbase = blockIdx.x * 64;
    const int tid = threadIdx.x, w = tid >> 5, lane = tid & 31;
    uint32_t (*Ps)[68] = (uint32_t(*)[68])(dyn + KS_WORDS + VS_WORDS + w * (16*68));
    const int g = h >> 2;                 // kv head (repeat = 4)
    const float scale = 0.125f;           // 1/sqrt(64)
    const int r0 = lane >> 2, qt = lane & 3;

    // Q fragments: 16 rows x 64 dims per warp, 8 k-chunks
    uint32_t qf[8][4];
    {
        const float* qp = qkv + (size_t)(b*TT + qbase + w*16) * QKV_N + h*HD;
#pragma unroll
        for (int kc = 0; kc < 8; kc++) {
            qf[kc][0] = f2tf32(qp[(size_t)r0*QKV_N + kc*8 + qt] * scale);
            qf[kc][1] = f2tf32(qp[(size_t)(r0+8)*QKV_N + kc*8 + qt] * scale);
            qf[kc][2] = f2tf32(qp[(size_t)r0*QKV_N + kc*8 + 4 + qt] * scale);
            qf[kc][3] = f2tf32(qp[(size_t)(r0+8)*QKV_N + kc*8 + 4 + qt] * scale);
        }
    }

    float o[8][4] = {};
    float m0 = -1e30f, m1 = -1e30f, l0 = 0.f, l1 = 0.f;

    const int ntiles = blockIdx.x + 1;
    for (int kt = 0; kt < ntiles; kt++) {
        const int kb = kt * 64;
        __syncthreads();
        // stage K,V (tf32)
        {
            const float* kp = qkv + (size_t)(b*TT + kb)*QKV_N + KV_OFF + g*HD;
            const float* vp = qkv + (size_t)(b*TT + kb)*QKV_N + V_OFF + g*HD;
            for (int e = tid; e < 1024; e += 128) {
                int r = e >> 4, c4 = (e & 15) * 4;
                float4 kv = *(const float4*)&kp[(size_t)r*QKV_N + c4];
                float4 vv = *(const float4*)&vp[(size_t)r*QKV_N + c4];
                uint4 k4 = {f2tf32(kv.x), f2tf32(kv.y), f2tf32(kv.z), f2tf32(kv.w)};
                uint4 v4 = {f2tf32(vv.x), f2tf32(vv.y), f2tf32(vv.z), f2tf32(vv.w)};
                *(uint4*)&Ks[r][c4] = k4;
                *(uint4*)&Vs[r][c4] = v4;
            }
        }
        __syncthreads();

        // S = Q @ K^T  (16 x 64 per warp)
        float s[8][4];
#pragma unroll
        for (int j = 0; j < 8; j++) { s[j][0]=s[j][1]=s[j][2]=s[j][3]=0.f; }
#pragma unroll
        for (int kc = 0; kc < 8; kc++) {
#pragma unroll
            for (int j = 0; j < 8; j++) {
                uint32_t bf[2];
                bf[0] = Ks[j*8 + r0][kc*8 + qt];
                bf[1] = Ks[j*8 + r0][kc*8 + 4 + qt];
                mma_tf32(s[j], qf[kc], bf);
            }
        }

        // causal mask on diagonal tile (kb == qbase)
        if (kt == ntiles - 1) {
            const int row0 = qbase + w*16 + r0, row1 = row0 + 8;
#pragma unroll
            for (int j = 0; j < 8; j++) {
                int col = kb + j*8 + 2*qt;
                if (col     > row0) s[j][0] = -1e30f;
                if (col + 1 > row0) s[j][1] = -1e30f;
                if (col     > row1) s[j][2] = -1e30f;
                if (col + 1 > row1) s[j][3] = -1e30f;
            }
        }

        // online softmax (rows r0, r0+8); quad reduction over lanes {1,2}
        float lm0 = -1e30f, lm1 = -1e30f;
#pragma unroll
        for (int j = 0; j < 8; j++) {
            lm0 = fmaxf(lm0, fmaxf(s[j][0], s[j][1]));
            lm1 = fmaxf(lm1, fmaxf(s[j][2], s[j][3]));
        }
        lm0 = fmaxf(lm0, __shfl_xor_sync(0xffffffffu, lm0, 1));
        lm0 = fmaxf(lm0, __shfl_xor_sync(0xffffffffu, lm0, 2));
        lm1 = fmaxf(lm1, __shfl_xor_sync(0xffffffffu, lm1, 1));
        lm1 = fmaxf(lm1, __shfl_xor_sync(0xffffffffu, lm1, 2));
        float m0n = fmaxf(m0, lm0), m1n = fmaxf(m1, lm1);
        float c0 = __expf(m0 - m0n), c1 = __expf(m1 - m1n);
        float ls0 = 0.f, ls1 = 0.f;
#pragma unroll
        for (int j = 0; j < 8; j++) {
            float p0 = __expf(s[j][0] - m0n), p1 = __expf(s[j][1] - m0n);
            float p2 = __expf(s[j][2] - m1n), p3 = __expf(s[j][3] - m1n);
            ls0 += p0 + p1; ls1 += p2 + p3;
            Ps[r0][j*8 + 2*qt]       = f2tf32(p0);
            Ps[r0][j*8 + 2*qt + 1]   = f2tf32(p1);
            Ps[r0+8][j*8 + 2*qt]     = f2tf32(p2);
            Ps[r0+8][j*8 + 2*qt + 1] = f2tf32(p3);
        }
        ls0 += __shfl_xor_sync(0xffffffffu, ls0, 1);
        ls0 += __shfl_xor_sync(0xffffffffu, ls0, 2);
        ls1 += __shfl_xor_sync(0xffffffffu, ls1, 1);
        ls1 += __shfl_xor_sync(0xffffffffu, ls1, 2);
        l0 = l0 * c0 + ls0; l1 = l1 * c1 + ls1;
        m0 = m0n; m1 = m1n;
#pragma unroll
        for (int jn = 0; jn < 8; jn++) {
            o[jn][0] *= c0; o[jn][1] *= c0; o[jn][2] *= c1; o[jn][3] *= c1;
        }
        __syncwarp();

        // O += P @ V
#pragma unroll
        for (int kc = 0; kc < 8; kc++) {
            uint32_t af[4];
            af[0] = Ps[r0][kc*8 + qt];
            af[1] = Ps[r0+8][kc*8 + qt];
            af[2] = Ps[r0][kc*8 + 4 + qt];
            af[3] = Ps[r0+8][kc*8 + 4 + qt];
#pragma unroll
            for (int jn = 0; jn < 8; jn++) {
                uint32_t bf[2];
                bf[0] = Vs[kc*8 + qt][jn*8 + r0];
                bf[1] = Vs[kc*8 + 4 + qt][jn*8 + r0];
                mma_tf32(o[jn], af, bf);
            }
        }
        __syncwarp();
    }

    const float inv0 = 1.f / l0, inv1 = 1.f / l1;
    const int grow = b*TT + qbase + w*16 + r0;
    float* op = out + (size_t)grow * DD + h*HD;
#pragma unroll
    for (int jn = 0; jn < 8; jn++) {
        float2 v0 = {o[jn][0]*inv0, o[jn][1]*inv0};
        float2 v1 = {o[jn][2]*inv1, o[jn][3]*inv1};
        *(float2*)&op[jn*8 + 2*qt] = v0;
        *(float2*)&op[(size_t)8*DD + jn*8 + 2*qt] = v1;
    }
}

// ---------------------------------------------------------------------------
extern "C" void kernel_launch(void* const* d_in, const int* in_sizes, int n_in,
                              void* d_out, int out_size)
{
    const float* x     = (const float*)d_in[0];
    const float* sinp  = (const float*)d_in[1];
    const float* cosp  = (const float*)d_in[2];
    const float* w_qkv = (const float*)d_in[3];
    const float* w_out = (const float*)d_in[4];
    float* out = (float*)d_out;

    float *qkv, *att;
    cudaGetSymbolAddress((void**)&qkv, g_qkv);
    cudaGetSymbolAddress((void**)&att, g_att);

    cudaFuncSetAttribute(attn_tc, cudaFuncAttributeMaxDynamicSharedMemorySize,
                         ATTN_SMEM);

    // 1) qkv = x @ w_qkv     [4096,2048] x [2048,3072]
    {
        dim3 grid(QKV_N / 128, MM / 128);
        gemm_tf32<<<grid, 256>>>(x, w_qkv, qkv, MM, QKV_N, DD);
    }
    // 2) RoPE on q,k slices
    {
        int total = MM * 40 * 32;
        rope_kernel<<<(total + 255) / 256, 256>>>(qkv, sinp, cosp);
    }
    // 3) causal GQA flash attention (tensor cores)
    {
        dim3 grid(TT / 64, NH, BB);
        attn_tc<<<grid, 128, ATTN_SMEM>>>(qkv, att);
    }
    // 4) out = att @ w_out    [4096,2048] x [2048,2048]
    {
        dim3 grid(DD / 128, MM / 128);
        gemm_tf32<<<grid, 256>>>(att, w_out, out, MM, DD, DD);
    }
}

// round 15
// speedup vs baseline: 4.6608x; 1.0718x over previous
#include <cuda_runtime.h>
#include <cuda_bf16.h>
#include <cstdint>

// Problem constants
#define BB 2
#define TT 2048
#define DD 2048
#define NH 32
#define NKV 8
#define HD 64
#define MM (BB*TT)            // 4096 rows
#define QKV_N 3072            // D + 2*KV_DIM
#define KV_OFF 2048
#define V_OFF 2560

// Scratch (allocation-free rule: __device__ globals)
__device__ float g_qkv[(size_t)MM * QKV_N];   // 50.3 MB
__device__ float g_att[(size_t)MM * DD];      // 33.5 MB (written tf32-rounded)
__device__ float g_xt [(size_t)MM * DD];      // 33.5 MB x, tf32-rounded
__device__ float g_wqt[(size_t)DD * QKV_N];   // 25.2 MB w_qkv, tf32-rounded
__device__ float g_wot[(size_t)DD * DD];      // 16.8 MB w_out, tf32-rounded

__device__ __forceinline__ uint32_t f2tf32(float x) {
    uint32_t r;
    asm("cvt.rna.tf32.f32 %0, %1;" : "=r"(r) : "f"(x));
    return r;
}

__device__ __forceinline__ void mma_tf32(float* d, const uint32_t* a, const uint32_t* b) {
    asm volatile(
        "mma.sync.aligned.m16n8k8.row.col.f32.tf32.tf32.f32 "
        "{%0,%1,%2,%3}, {%4,%5,%6,%7}, {%8,%9}, {%0,%1,%2,%3};"
        : "+f"(d[0]), "+f"(d[1]), "+f"(d[2]), "+f"(d[3])
        : "r"(a[0]), "r"(a[1]), "r"(a[2]), "r"(a[3]), "r"(b[0]), "r"(b[1]));
}

__device__ __forceinline__ uint32_t s2u(const void* p) {
    return (uint32_t)__cvta_generic_to_shared(p);
}
__device__ __forceinline__ void cpa16(uint32_t dst, const void* src) {
    asm volatile("cp.async.cg.shared.global [%0], [%1], 16;\n" :: "r"(dst), "l"(src));
}
#define CP_COMMIT() asm volatile("cp.async.commit_group;\n" ::: "memory")
#define CP_WAIT0()  asm volatile("cp.async.wait_group 0;\n" ::: "memory")

// ---------------------------------------------------------------------------
// Elementwise fp32 -> tf32-rounded-fp32 (pre-pass so GEMM can use cp.async)
// ---------------------------------------------------------------------------
__global__ void round_tf32(const float* __restrict__ in, float* __restrict__ o, int n4)
{
    int i = blockIdx.x * blockDim.x + threadIdx.x;
    if (i >= n4) return;
    float4 v = *(const float4*)&in[(size_t)i * 4];
    uint4 r = {f2tf32(v.x), f2tf32(v.y), f2tf32(v.z), f2tf32(v.w)};
    *(uint4*)&o[(size_t)i * 4] = r;
}

// ---------------------------------------------------------------------------
// TF32 tensor-core GEMM, cp.async double-buffered.
// Inputs MUST be pre-rounded to tf32 (bit pattern in fp32).
// C[M,N] = A[M,K] * B[K,N], row-major. 128x128x32 tile, 256 thr, 8 warps.
// Dynamic smem: 2 stages x (A 128x36 + B 32x136) words = 71680 B
// ---------------------------------------------------------------------------
#define ASZ (128*36)
#define BSZ (32*136)
#define GEMM_SMEM (2*(ASZ+BSZ)*4)

__global__ __launch_bounds__(256, 2) void gemm_tf32p(
    const float* __restrict__ A, const float* __restrict__ Bw,
    float* __restrict__ C, int Nn, int Kk)
{
    extern __shared__ uint32_t sm[];
    const int tid  = threadIdx.x;
    const int wid  = tid >> 5;
    const int lane = tid & 31;
    const int wm   = wid & 3;
    const int wn   = wid >> 2;
    const int rowBase = blockIdx.y * 128;
    const int colBase = blockIdx.x * 128;

    const int ca = (tid & 7) * 4;     // A col
    const int ra = tid >> 3;          // A row base (stride 32)
    const int cb = (tid & 31) * 4;    // B col
    const int rb = tid >> 5;          // B row base (stride 8)

    float acc[2][8][4] = {};

    // stage load: all cp.async
    auto load_stage = [&](int s, int k0) {
        uint32_t* As = sm + s * (ASZ + BSZ);
        uint32_t* Bs = As + ASZ;
#pragma unroll
        for (int it = 0; it < 4; it++) {
            const int r = ra + it * 32;
            cpa16(s2u(&As[r * 36 + ca]),
                  &A[(size_t)(rowBase + r) * Kk + k0 + ca]);
        }
#pragma unroll
        for (int it = 0; it < 4; it++) {
            const int r = rb + it * 8;
            cpa16(s2u(&Bs[r * 136 + cb]),
                  &Bw[(size_t)(k0 + r) * Nn + colBase + cb]);
        }
    };

    load_stage(0, 0);
    CP_COMMIT();

    int stage = 0;
    for (int k0 = 0; k0 < Kk; k0 += 32) {
        CP_WAIT0();
        __syncthreads();                 // loads of `stage` visible; prev compute done
        if (k0 + 32 < Kk) {
            load_stage(stage ^ 1, k0 + 32);
            CP_COMMIT();
        }
        const uint32_t* As = sm + stage * (ASZ + BSZ);
        const uint32_t* Bs = As + ASZ;

#pragma unroll
        for (int kk = 0; kk < 4; kk++) {
            const int k = kk * 8;
            uint32_t a[2][4];
#pragma unroll
            for (int i = 0; i < 2; i++) {
                const int rr0 = wm * 32 + i * 16 + (lane >> 2);
                const int cc0 = k + (lane & 3);
                a[i][0] = As[rr0 * 36 + cc0];
                a[i][1] = As[(rr0 + 8) * 36 + cc0];
                a[i][2] = As[rr0 * 36 + cc0 + 4];
                a[i][3] = As[(rr0 + 8) * 36 + cc0 + 4];
            }
            uint32_t b[8][2];
#pragma unroll
            for (int j = 0; j < 8; j++) {
                const int nc = wn * 64 + j * 8 + (lane >> 2);
                b[j][0] = Bs[(k + (lane & 3)) * 136 + nc];
                b[j][1] = Bs[(k + 4 + (lane & 3)) * 136 + nc];
            }
#pragma unroll
            for (int i = 0; i < 2; i++)
#pragma unroll
                for (int j = 0; j < 8; j++)
                    mma_tf32(acc[i][j], a[i], b[j]);
        }
        stage ^= 1;
    }

#pragma unroll
    for (int i = 0; i < 2; i++) {
        const int row = rowBase + wm * 32 + i * 16 + (lane >> 2);
#pragma unroll
        for (int j = 0; j < 8; j++) {
            const int col = colBase + wn * 64 + j * 8 + (lane & 3) * 2;
            float2 v0 = {acc[i][j][0], acc[i][j][1]};
            float2 v1 = {acc[i][j][2], acc[i][j][3]};
            *(float2*)&C[(size_t)row * Nn + col] = v0;
            *(float2*)&C[(size_t)(row + 8) * Nn + col] = v1;
        }
    }
}

// ---------------------------------------------------------------------------
// RoPE applied in-place to q ([0,2048)) and k ([2048,2560)) slices of g_qkv.
// ---------------------------------------------------------------------------
__global__ void rope_kernel(float* __restrict__ qkv,
                            const float* __restrict__ sinp,
                            const float* __restrict__ cosp)
{
    int idx = blockIdx.x * blockDim.x + threadIdx.x;
    const int total = MM * 40 * 32;
    if (idx >= total) return;
    int d    = idx & 31;
    int head = (idx >> 5) % 40;
    int row  = idx / (40 * 32);
    int t    = row % TT;
    int col  = (head < NH) ? head * HD : KV_OFF + (head - NH) * HD;
    float* p = qkv + (size_t)row * QKV_N + col;
    float u1 = p[d], u2 = p[d + 32];
    float c = cosp[t * HD + d];
    float s = sinp[t * HD + d];
    p[d]      = u1 * c - u2 * s;
    p[d + 32] = u2 * c + u1 * s;
}

// ---------------------------------------------------------------------------
// Tensor-core causal flash attention (TF32 mma.sync).
// grid = (T/64, NH, B), block = 128 (4 warps, 16 q-rows each).
// Output written tf32-rounded so the out-GEMM can cp.async it directly.
// ---------------------------------------------------------------------------
#define KS_WORDS (64*68)
#define VS_WORDS (64*72)
#define ATTN_SMEM ((KS_WORDS + VS_WORDS + 4*16*68) * 4)

__global__ __launch_bounds__(128) void attn_tc(
    const float* __restrict__ qkv, float* __restrict__ out)
{
    extern __shared__ uint32_t dyn[];
    uint32_t (*Ks)[68] = (uint32_t(*)[68])dyn;
    uint32_t (*Vs)[72] = (uint32_t(*)[72])(dyn + KS_WORDS);
    const int b = blockIdx.z, h = blockIdx.y;
    const int qbase = blockIdx.x * 64;
    const int tid = threadIdx.x, w = tid >> 5, lane = tid & 31;
    uint32_t (*Ps)[68] = (uint32_t(*)[68])(dyn + KS_WORDS + VS_WORDS + w * (16*68));
    const int g = h >> 2;                 // kv head (repeat = 4)
    const float scale = 0.125f;           // 1/sqrt(64)
    const int r0 = lane >> 2, qt = lane & 3;

    uint32_t qf[8][4];
    {
        const float* qp = qkv + (size_t)(b*TT + qbase + w*16) * QKV_N + h*HD;
#pragma unroll
        for (int kc = 0; kc < 8; kc++) {
            qf[kc][0] = f2tf32(qp[(size_t)r0*QKV_N + kc*8 + qt] * scale);
            qf[kc][1] = f2tf32(qp[(size_t)(r0+8)*QKV_N + kc*8 + qt] * scale);
            qf[kc][2] = f2tf32(qp[(size_t)r0*QKV_N + kc*8 + 4 + qt] * scale);
            qf[kc][3] = f2tf32(qp[(size_t)(r0+8)*QKV_N + kc*8 + 4 + qt] * scale);
        }
    }

    float o[8][4] = {};
    float m0 = -1e30f, m1 = -1e30f, l0 = 0.f, l1 = 0.f;

    const int ntiles = blockIdx.x + 1;
    for (int kt = 0; kt < ntiles; kt++) {
        const int kb = kt * 64;
        __syncthreads();
        {
            const float* kp = qkv + (size_t)(b*TT + kb)*QKV_N + KV_OFF + g*HD;
            const float* vp = qkv + (size_t)(b*TT + kb)*QKV_N + V_OFF + g*HD;
            for (int e = tid; e < 1024; e += 128) {
                int r = e >> 4, c4 = (e & 15) * 4;
                float4 kv = *(const float4*)&kp[(size_t)r*QKV_N + c4];
                float4 vv = *(const float4*)&vp[(size_t)r*QKV_N + c4];
                uint4 k4 = {f2tf32(kv.x), f2tf32(kv.y), f2tf32(kv.z), f2tf32(kv.w)};
                uint4 v4 = {f2tf32(vv.x), f2tf32(vv.y), f2tf32(vv.z), f2tf32(vv.w)};
                *(uint4*)&Ks[r][c4] = k4;
                *(uint4*)&Vs[r][c4] = v4;
            }
        }
        __syncthreads();

        float s[8][4];
#pragma unroll
        for (int j = 0; j < 8; j++) { s[j][0]=s[j][1]=s[j][2]=s[j][3]=0.f; }
#pragma unroll
        for (int kc = 0; kc < 8; kc++) {
#pragma unroll
            for (int j = 0; j < 8; j++) {
                uint32_t bf[2];
                bf[0] = Ks[j*8 + r0][kc*8 + qt];
                bf[1] = Ks[j*8 + r0][kc*8 + 4 + qt];
                mma_tf32(s[j], qf[kc], bf);
            }
        }

        if (kt == ntiles - 1) {
            const int row0 = qbase + w*16 + r0, row1 = row0 + 8;
#pragma unroll
            for (int j = 0; j < 8; j++) {
                int col = kb + j*8 + 2*qt;
                if (col     > row0) s[j][0] = -1e30f;
                if (col + 1 > row0) s[j][1] = -1e30f;
                if (col     > row1) s[j][2] = -1e30f;
                if (col + 1 > row1) s[j][3] = -1e30f;
            }
        }

        float lm0 = -1e30f, lm1 = -1e30f;
#pragma unroll
        for (int j = 0; j < 8; j++) {
            lm0 = fmaxf(lm0, fmaxf(s[j][0], s[j][1]));
            lm1 = fmaxf(lm1, fmaxf(s[j][2], s[j][3]));
        }
        lm0 = fmaxf(lm0, __shfl_xor_sync(0xffffffffu, lm0, 1));
        lm0 = fmaxf(lm0, __shfl_xor_sync(0xffffffffu, lm0, 2));
        lm1 = fmaxf(lm1, __shfl_xor_sync(0xffffffffu, lm1, 1));
        lm1 = fmaxf(lm1, __shfl_xor_sync(0xffffffffu, lm1, 2));
        float m0n = fmaxf(m0, lm0), m1n = fmaxf(m1, lm1);
        float c0 = __expf(m0 - m0n), c1 = __expf(m1 - m1n);
        float ls0 = 0.f, ls1 = 0.f;
#pragma unroll
        for (int j = 0; j < 8; j++) {
            float p0 = __expf(s[j][0] - m0n), p1 = __expf(s[j][1] - m0n);
            float p2 = __expf(s[j][2] - m1n), p3 = __expf(s[j][3] - m1n);
            ls0 += p0 + p1; ls1 += p2 + p3;
            Ps[r0][j*8 + 2*qt]       = f2tf32(p0);
            Ps[r0][j*8 + 2*qt + 1]   = f2tf32(p1);
            Ps[r0+8][j*8 + 2*qt]     = f2tf32(p2);
            Ps[r0+8][j*8 + 2*qt + 1] = f2tf32(p3);
        }
        ls0 += __shfl_xor_sync(0xffffffffu, ls0, 1);
        ls0 += __shfl_xor_sync(0xffffffffu, ls0, 2);
        ls1 += __shfl_xor_sync(0xffffffffu, ls1, 1);
        ls1 += __shfl_xor_sync(0xffffffffu, ls1, 2);
        l0 = l0 * c0 + ls0; l1 = l1 * c1 + ls1;
        m0 = m0n; m1 = m1n;
#pragma unroll
        for (int jn = 0; jn < 8; jn++) {
            o[jn][0] *= c0; o[jn][1] *= c0; o[jn][2] *= c1; o[jn][3] *= c1;
        }
        __syncwarp();

#pragma unroll
        for (int kc = 0; kc < 8; kc++) {
            uint32_t af[4];
            af[0] = Ps[r0][kc*8 + qt];
            af[1] = Ps[r0+8][kc*8 + qt];
            af[2] = Ps[r0][kc*8 + 4 + qt];
            af[3] = Ps[r0+8][kc*8 + 4 + qt];
#pragma unroll
            for (int jn = 0; jn < 8; jn++) {
                uint32_t bf[2];
                bf[0] = Vs[kc*8 + qt][jn*8 + r0];
                bf[1] = Vs[kc*8 + 4 + qt][jn*8 + r0];
                mma_tf32(o[jn], af, bf);
            }
        }
        __syncwarp();
    }

    const float inv0 = 1.f / l0, inv1 = 1.f / l1;
    const int grow = b*TT + qbase + w*16 + r0;
    float* op = out + (size_t)grow * DD + h*HD;
#pragma unroll
    for (int jn = 0; jn < 8; jn++) {
        // tf32-round the attention output so out-GEMM needs no conversion
        float2 v0 = {__uint_as_float(f2tf32(o[jn][0]*inv0)),
                     __uint_as_float(f2tf32(o[jn][1]*inv0))};
        float2 v1 = {__uint_as_float(f2tf32(o[jn][2]*inv1)),
                     __uint_as_float(f2tf32(o[jn][3]*inv1))};
        *(float2*)&op[jn*8 + 2*qt] = v0;
        *(float2*)&op[(size_t)8*DD + jn*8 + 2*qt] = v1;
    }
}

// ---------------------------------------------------------------------------
extern "C" void kernel_launch(void* const* d_in, const int* in_sizes, int n_in,
                              void* d_out, int out_size)
{
    const float* x     = (const float*)d_in[0];
    const float* sinp  = (const float*)d_in[1];
    const float* cosp  = (const float*)d_in[2];
    const float* w_qkv = (const float*)d_in[3];
    const float* w_out = (const float*)d_in[4];
    float* out = (float*)d_out;

    float *qkv, *att, *xt, *wqt, *wot;
    cudaGetSymbolAddress((void**)&qkv, g_qkv);
    cudaGetSymbolAddress((void**)&att, g_att);
    cudaGetSymbolAddress((void**)&xt,  g_xt);
    cudaGetSymbolAddress((void**)&wqt, g_wqt);
    cudaGetSymbolAddress((void**)&wot, g_wot);

    cudaFuncSetAttribute(attn_tc, cudaFuncAttributeMaxDynamicSharedMemorySize,
                         ATTN_SMEM);
    cudaFuncSetAttribute(gemm_tf32p, cudaFuncAttributeMaxDynamicSharedMemorySize,
                         GEMM_SMEM);

    // 0) pre-round GEMM inputs to tf32 bit patterns
    {
        int n4x = MM * DD / 4, n4q = DD * QKV_N / 4, n4o = DD * DD / 4;
        round_tf32<<<(n4x + 255) / 256, 256>>>(x, xt, n4x);
        round_tf32<<<(n4q + 255) / 256, 256>>>(w_qkv, wqt, n4q);
        round_tf32<<<(n4o + 255) / 256, 256>>>(w_out, wot, n4o);
    }
    // 1) qkv = xt @ wqt     [4096,2048] x [2048,3072]
    {
        dim3 grid(QKV_N / 128, MM / 128);
        gemm_tf32p<<<grid, 256, GEMM_SMEM>>>(xt, wqt, qkv, QKV_N, DD);
    }
    // 2) RoPE on q,k slices
    {
        int total = MM * 40 * 32;
        rope_kernel<<<(total + 255) / 256, 256>>>(qkv, sinp, cosp);
    }
    // 3) causal GQA flash attention (tensor cores, writes tf32-rounded att)
    {
        dim3 grid(TT / 64, NH, BB);
        attn_tc<<<grid, 128, ATTN_SMEM>>>(qkv, att);
    }
    // 4) out = att @ wot    [4096,2048] x [2048,2048]
    {
        dim3 grid(DD / 128, MM / 128);
        gemm_tf32p<<<grid, 256, GEMM_SMEM>>>(att, wot, out, DD, DD);
    }
}